// round 5
// baseline (speedup 1.0000x reference)
#include <cuda_runtime.h>
#include <cstdint>

// Grapher: B=128, S=1024, H=768, C=150, N=8, sep id 3. One block per batch.
// fp32 with packed f32x2 FFMA. Round-5: token-parallel segment means (3 token
// groups x 192 float4 cols, partials in the W2 smem region), deferred W2
// cp.async overlapped with GEMM1/GEMM2 via wait_group split.

#define B_   128
#define S_   1024
#define H_   768
#define C_   150
#define NN   8
#define SEPID 3
#define NTHR 608          // 19 warps

// shared memory layout (float offsets)
#define OFF_WM    0        // 150*152 = 22800 (cols 150,151 zero pad)
#define OFF_W2    22800    // 150*152 ; during means: partials P[3][8][776] = 18624
#define OFF_X     45600    // 9728: meansT[768][8] -> GEMM1 partials -> XT[152][64]
#define OFF_G     55328    // 8*152
#define OFF_B1    56544    // 152
#define OFF_BM    56696    // 152
#define OFF_B2    56848    // 152
#define OFF_BND   57000    // 16 ints
#define SMEM_FLOATS 57016
#define SMEM_BYTES (SMEM_FLOATS * 4)   // 228064 <= 232448

typedef unsigned long long u64;

__device__ __forceinline__ uint32_t sptr(const void* p) {
    return (uint32_t)__cvta_generic_to_shared(p);
}
__device__ __forceinline__ void cp8(uint32_t s, const void* g) {
    asm volatile("cp.async.ca.shared.global [%0], [%1], 8;" :: "r"(s), "l"(g));
}
#define CP_COMMIT() asm volatile("cp.async.commit_group;" ::: "memory")
#define CP_WAIT1()  asm volatile("cp.async.wait_group 1;" ::: "memory")
#define CP_WAIT0()  asm volatile("cp.async.wait_group 0;" ::: "memory")

__device__ __forceinline__ void ffma2(u64& d, u64 a, u64 b) {
    asm("fma.rn.f32x2 %0, %1, %2, %0;" : "+l"(d) : "l"(a), "l"(b));
}
__device__ __forceinline__ u64 add2(u64 a, u64 b) {
    u64 r; asm("add.rn.f32x2 %0, %1, %2;" : "=l"(r) : "l"(a), "l"(b)); return r;
}
__device__ __forceinline__ u64 dup2(float x) {
    u64 r; asm("mov.b64 %0, {%1, %1};" : "=l"(r) : "f"(x)); return r;
}
__device__ __forceinline__ u64 pack2(float lo, float hi) {
    u64 r; asm("mov.b64 %0, {%1, %2};" : "=l"(r) : "f"(lo), "f"(hi)); return r;
}
__device__ __forceinline__ void unpack2(u64 v, float& lo, float& hi) {
    asm("mov.b64 {%0, %1}, %2;" : "=f"(lo), "=f"(hi) : "l"(v));
}
__device__ __forceinline__ u64 lds64(uint32_t a) {
    u64 v; asm volatile("ld.shared.u64 %0, [%1];" : "=l"(v) : "r"(a)); return v;
}
__device__ __forceinline__ void lds_v2(uint32_t a, u64& x, u64& y) {
    asm volatile("ld.shared.v2.u64 {%0, %1}, [%2];" : "=l"(x), "=l"(y) : "r"(a));
}
__device__ __forceinline__ void sts64(uint32_t a, u64 v) {
    asm volatile("st.shared.u64 [%0], %1;" :: "r"(a), "l"(v) : "memory");
}

// 64x152 = XT(150 k) @ W(150x152); warp = 8-col group, lane = row pair.
__device__ __forceinline__ void gemm_pair(uint32_t xt_b, uint32_t w_b, uint32_t bias_b,
                                          int rg, int c0, u64 acc[2][4])
{
#pragma unroll
    for (int cp = 0; cp < 4; cp++) {
        u64 bv = lds64(bias_b + (uint32_t)(c0 + 2 * cp) * 4u);
        acc[0][cp] = bv; acc[1][cp] = bv;
    }
#pragma unroll 6
    for (int k = 0; k < C_; k++) {
        u64 xp = lds64(xt_b + (uint32_t)(k * 64 + 2 * rg) * 4u);
        float x0, x1; unpack2(xp, x0, x1);
        u64 d0 = dup2(x0), d1 = dup2(x1);
        u64 w0, w1, w2, w3;
        uint32_t wa = w_b + (uint32_t)(k * 152 + c0) * 4u;
        lds_v2(wa, w0, w1);
        lds_v2(wa + 16u, w2, w3);
        ffma2(acc[0][0], d0, w0); ffma2(acc[0][1], d0, w1);
        ffma2(acc[0][2], d0, w2); ffma2(acc[0][3], d0, w3);
        ffma2(acc[1][0], d1, w0); ffma2(acc[1][1], d1, w1);
        ffma2(acc[1][2], d1, w2); ffma2(acc[1][3], d1, w3);
    }
}

__global__ __launch_bounds__(NTHR, 1)
void grapher_kernel(const int* __restrict__ ids,
                    const float* __restrict__ feat,
                    const float* __restrict__ W1, const float* __restrict__ b1,
                    const float* __restrict__ Wm, const float* __restrict__ bm,
                    const float* __restrict__ W2, const float* __restrict__ b2,
                    float* __restrict__ out)
{
    extern __shared__ float sm[];
    float* sWm = sm + OFF_WM;
    float* sW2 = sm + OFF_W2;            // P scratch during means
    float* sX  = sm + OFF_X;
    float* sG  = sm + OFF_G;
    float* sB1 = sm + OFF_B1;
    float* sBM = sm + OFF_BM;
    float* sB2 = sm + OFF_B2;
    int*   sBnd = (int*)(sm + OFF_BND);

    const int tid = threadIdx.x;
    const int b   = blockIdx.x;
    const uint32_t wm_b = sptr(sWm);
    const uint32_t w2_b = sptr(sW2);
    const uint32_t x_b  = sptr(sX);

    // ---------- cp.async group A: Wm (dest stride 152, src 150) ----------
    for (int m = tid; m < C_ * 75; m += NTHR) {
        int r = m / 75, cl = m - r * 75;
        cp8(wm_b + (uint32_t)(r * 152 + 2 * cl) * 4u, Wm + r * C_ + 2 * cl);
    }
    CP_COMMIT();
    if (tid < C_) { sWm[tid * 152 + 150] = 0.f; sWm[tid * 152 + 151] = 0.f; }

    // ---------- separator scan (warp 0) + bias loads ----------
    if (tid < 32) {
        const int lane = tid;
        if (lane < 16) sBnd[lane] = S_;
        __syncwarp();
        const int4* rp = (const int4*)(ids + (size_t)b * S_) + lane * 8;
        int4 v[8];
        int cnt = 0;
#pragma unroll
        for (int q = 0; q < 8; q++) {
            v[q] = rp[q];
            cnt += (v[q].x == SEPID) + (v[q].y == SEPID) +
                   (v[q].z == SEPID) + (v[q].w == SEPID);
        }
        int pre = cnt;
#pragma unroll
        for (int off = 1; off < 32; off <<= 1) {
            int t = __shfl_up_sync(0xffffffffu, pre, off);
            if (lane >= off) pre += t;
        }
        int run = pre - cnt;
#pragma unroll
        for (int q = 0; q < 8; q++) {
            int base = lane * 32 + q * 4;
            if (v[q].x == SEPID) { run++; if (run <= NN) sBnd[run] = base + 0; }
            if (v[q].y == SEPID) { run++; if (run <= NN) sBnd[run] = base + 1; }
            if (v[q].z == SEPID) { run++; if (run <= NN) sBnd[run] = base + 2; }
            if (v[q].w == SEPID) { run++; if (run <= NN) sBnd[run] = base + 3; }
        }
    } else if (tid >= 448 && tid < 448 + 152) {
        int i = tid - 448;
        sB1[i] = (i < C_) ? b1[i] : 0.f;
        sBM[i] = (i < C_) ? bm[i] : 0.f;
        sB2[i] = (i < C_) ? b2[i] : 0.f;
    }
    __syncthreads();

    // ---------- segment partial sums: 3 token groups x 192 float4 cols ----------
    // P[tg][n][776] in the W2 region; each thread owns (tg, col), 8 accumulators.
    if (tid < 576) {
        const int tg  = tid / 192;
        const int col = tid - tg * 192;
        int bnd[9];
        bnd[0] = -1;
#pragma unroll
        for (int n = 1; n <= NN; n++) bnd[n] = sBnd[n];
        const float4* f4 = (const float4*)(feat + (size_t)b * S_ * H_) + col;
        float4 acc[8];
#pragma unroll
        for (int n = 0; n < NN; n++) acc[n] = make_float4(0.f, 0.f, 0.f, 0.f);
#pragma unroll 1
        for (int n = 0; n < NN; n++) {
            int hi = bnd[n + 1];
            for (int t = bnd[n] + 1 + tg; t < hi; t += 3) {
                float4 v = f4[t * 192];
                acc[n].x += v.x; acc[n].y += v.y;
                acc[n].z += v.z; acc[n].w += v.w;
            }
        }
        float* P = sW2 + tg * 6208 + col * 4;
#pragma unroll
        for (int n = 0; n < NN; n++)
            *(float4*)(P + n * 776) = acc[n];
    }
    __syncthreads();

    // ---------- combine groups + 1/len -> meansT[k][8] in sX ----------
    {
        float inv[8];
#pragma unroll
        for (int n = 0; n < NN; n++) {
            int lo = (n == 0) ? 0 : sBnd[n] + 1;
            int len = sBnd[n + 1] - lo;
            if (len < 1) len = 1;
            inv[n] = 1.0f / (float)len;
        }
        for (int k = tid; k < H_; k += NTHR) {
            const float* P = sW2 + k;
#pragma unroll
            for (int n = 0; n < NN; n++) {
                float s = P[n * 776] + P[6208 + n * 776] + P[12416 + n * 776];
                sX[k * 8 + n] = s * inv[n];
            }
        }
    }
    __syncthreads();                      // P reads done; W2 region free

    // ---------- cp.async group B: W2 (overlaps GEMM1/pair/GEMM2) ----------
    for (int m = tid; m < C_ * 75; m += NTHR) {
        int r = m / 75, cl = m - r * 75;
        cp8(w2_b + (uint32_t)(r * 152 + 2 * cl) * 4u, W2 + r * C_ + 2 * cl);
    }
    CP_COMMIT();
    if (tid < C_) { sW2[tid * 152 + 150] = 0.f; sW2[tid * 152 + 151] = 0.f; }

    // ---------- GEMM1: g[n][c] = sum_k meansT[k][n] * W1[k][c] ----------
    u64 g_acc[2][4];
    int ks = 0, cpair = 0;
    if (tid < 600) {
        ks = tid / 75; cpair = tid - ks * 75;
#pragma unroll
        for (int cc = 0; cc < 2; cc++)
#pragma unroll
            for (int q = 0; q < 4; q++) g_acc[cc][q] = 0ull;
        const float2* wrow = (const float2*)(W1 + (size_t)(ks * 96) * C_) + cpair;
#pragma unroll 4
        for (int kk = 0; kk < 96; kk++) {
            int k = ks * 96 + kk;
            float2 w = __ldg(wrow + kk * 75);
            u64 dw0 = dup2(w.x), dw1 = dup2(w.y);
            u64 m01, m23, m45, m67;
            uint32_t ma = x_b + (uint32_t)(k * 8) * 4u;
            lds_v2(ma, m01, m23);
            lds_v2(ma + 16u, m45, m67);
            ffma2(g_acc[0][0], m01, dw0); ffma2(g_acc[0][1], m23, dw0);
            ffma2(g_acc[0][2], m45, dw0); ffma2(g_acc[0][3], m67, dw0);
            ffma2(g_acc[1][0], m01, dw1); ffma2(g_acc[1][1], m23, dw1);
            ffma2(g_acc[1][2], m45, dw1); ffma2(g_acc[1][3], m67, dw1);
        }
    }
    __syncthreads();                      // meansT reads done; reuse region
    if (tid < 600) {                      // partials P[ks][e][150]
#pragma unroll
        for (int cc = 0; cc < 2; cc++)
#pragma unroll
            for (int q = 0; q < 4; q++)
                sts64(x_b + (uint32_t)(ks * 1200 + (cc * 4 + q) * 150 + 2 * cpair) * 4u,
                      g_acc[cc][q]);
    }
    __syncthreads();
    if (tid < 600) {                      // reduce 8 slices -> sG
        u64 s = lds64(x_b + (uint32_t)(2 * tid) * 4u);
#pragma unroll
        for (int k8 = 1; k8 < 8; k8++)
            s = add2(s, lds64(x_b + (uint32_t)(k8 * 1200 + 2 * tid) * 4u));
        int e = tid / 75, cp2 = tid - e * 75;
        int cc = e >> 2, q = e & 3, c = 2 * cp2 + cc;
        float lo, hi; unpack2(s, lo, hi);
        sG[(2 * q + 0) * 152 + c] = lo;
        sG[(2 * q + 1) * 152 + c] = hi;
    }
    CP_WAIT1();                           // Wm (group A) resident; W2 may be in flight
    __syncthreads();

    // ---------- pair build: XT[c][p] = relu(g_i[c] - g_j[c] + b1[c]) ----------
    const int cg = tid >> 5;              // warp -> col group of 8
    const int rg = tid & 31;              // row pair 2rg, 2rg+1
    const int c0 = cg * 8;
    {
        float v[2][8];
#pragma unroll
        for (int r = 0; r < 2; r++) {
            int p = 2 * rg + r;
            int i = p >> 3, j = p & 7;
            float4 ga0 = *(const float4*)(sG + i * 152 + c0);
            float4 ga1 = *(const float4*)(sG + i * 152 + c0 + 4);
            float4 gb0 = *(const float4*)(sG + j * 152 + c0);
            float4 gb1 = *(const float4*)(sG + j * 152 + c0 + 4);
            float4 ba  = *(const float4*)(sB1 + c0);
            float4 bb  = *(const float4*)(sB1 + c0 + 4);
            v[r][0] = fmaxf(ga0.x - gb0.x + ba.x, 0.f);
            v[r][1] = fmaxf(ga0.y - gb0.y + ba.y, 0.f);
            v[r][2] = fmaxf(ga0.z - gb0.z + ba.z, 0.f);
            v[r][3] = fmaxf(ga0.w - gb0.w + ba.w, 0.f);
            v[r][4] = fmaxf(ga1.x - gb1.x + bb.x, 0.f);
            v[r][5] = fmaxf(ga1.y - gb1.y + bb.y, 0.f);
            v[r][6] = fmaxf(ga1.z - gb1.z + bb.z, 0.f);
            v[r][7] = fmaxf(ga1.w - gb1.w + bb.w, 0.f);
        }
#pragma unroll
        for (int ccj = 0; ccj < 8; ccj++)
            sts64(x_b + (uint32_t)((c0 + ccj) * 64 + 2 * rg) * 4u,
                  pack2(v[0][ccj], v[1][ccj]));
    }
    __syncthreads();

    // ---------- GEMM2: y = relu(x @ Wm + bm) ----------
    u64 acc[2][4];
    gemm_pair(x_b, wm_b, sptr(sBM), rg, c0, acc);
    __syncthreads();                      // all x reads done
#pragma unroll
    for (int r = 0; r < 2; r++) {
        int p = 2 * rg + r;
#pragma unroll
        for (int cp = 0; cp < 4; cp++) {
            float lo, hi; unpack2(acc[r][cp], lo, hi);
            sX[(c0 + 2 * cp + 0) * 64 + p] = fmaxf(lo, 0.f);
            sX[(c0 + 2 * cp + 1) * 64 + p] = fmaxf(hi, 0.f);
        }
    }
    CP_WAIT0();                           // W2 (group B) resident
    __syncthreads();

    // ---------- GEMM3: out = y @ W2 + b2 ----------
    gemm_pair(x_b, w2_b, sptr(sB2), rg, c0, acc);

    const int ncp = (cg < 18) ? 4 : 3;    // col group 18 covers 144..149
#pragma unroll
    for (int r = 0; r < 2; r++) {
        int p = 2 * rg + r;
        float* o = out + ((size_t)p * B_ + b) * C_ + c0;
        for (int cp = 0; cp < ncp; cp++) {
            float lo, hi; unpack2(acc[r][cp], lo, hi);
            *(float2*)(o + 2 * cp) = make_float2(lo, hi);
        }
    }
}

extern "C" void kernel_launch(void* const* d_in, const int* in_sizes, int n_in,
                              void* d_out, int out_size)
{
    const int*   ids  = (const int*)d_in[0];
    const float* feat = (const float*)d_in[1];
    const float* W1 = (const float*)d_in[2];
    const float* b1 = (const float*)d_in[3];
    const float* Wm = (const float*)d_in[4];
    const float* bm = (const float*)d_in[5];
    const float* W2 = (const float*)d_in[6];
    const float* b2 = (const float*)d_in[7];
    float* out = (float*)d_out;

    cudaFuncSetAttribute(grapher_kernel,
                         cudaFuncAttributeMaxDynamicSharedMemorySize, SMEM_BYTES);
    grapher_kernel<<<B_, NTHR, SMEM_BYTES>>>(ids, feat, W1, b1, Wm, bm, W2, b2, out);
}

// round 6
// speedup vs baseline: 1.0367x; 1.0367x over previous
#include <cuda_runtime.h>
#include <cstdint>

// Grapher: B=128, S=1024, H=768, C=150, N=8, sep id 3. One block per batch.
// fp32 with packed f32x2 FFMA. Round-6: software-pipelined GEMM inner loops
// (depth-3 LDS pipeline in the pair GEMMs, double-buffered LDG groups in GEMM1).

#define B_   128
#define S_   1024
#define H_   768
#define C_   150
#define NN   8
#define SEPID 3
#define NTHR 608          // 19 warps

// shared memory layout (float offsets)
#define OFF_WM    0        // 150*152 = 22800 (cols 150,151 zero pad)
#define OFF_W2    22800    // 150*152
#define OFF_X     45600    // 9728: meansT[768][8] -> GEMM1 partials -> XT[152][64]
#define OFF_G     55328    // 8*152
#define OFF_B1    56544    // 152
#define OFF_BM    56696    // 152
#define OFF_B2    56848    // 152
#define OFF_BND   57000    // 16 ints
#define SMEM_FLOATS 57016
#define SMEM_BYTES (SMEM_FLOATS * 4)   // 228064 <= 232448

typedef unsigned long long u64;

__device__ __forceinline__ uint32_t sptr(const void* p) {
    return (uint32_t)__cvta_generic_to_shared(p);
}
__device__ __forceinline__ void cp8(uint32_t s, const void* g) {
    asm volatile("cp.async.ca.shared.global [%0], [%1], 8;" :: "r"(s), "l"(g));
}
#define CP_COMMIT() asm volatile("cp.async.commit_group;" ::: "memory")
#define CP_WAIT0()  asm volatile("cp.async.wait_group 0;" ::: "memory")

__device__ __forceinline__ void ffma2(u64& d, u64 a, u64 b) {
    asm("fma.rn.f32x2 %0, %1, %2, %0;" : "+l"(d) : "l"(a), "l"(b));
}
__device__ __forceinline__ u64 add2(u64 a, u64 b) {
    u64 r; asm("add.rn.f32x2 %0, %1, %2;" : "=l"(r) : "l"(a), "l"(b)); return r;
}
__device__ __forceinline__ u64 dup2(float x) {
    u64 r; asm("mov.b64 %0, {%1, %1};" : "=l"(r) : "f"(x)); return r;
}
__device__ __forceinline__ u64 pack2(float lo, float hi) {
    u64 r; asm("mov.b64 %0, {%1, %2};" : "=l"(r) : "f"(lo), "f"(hi)); return r;
}
__device__ __forceinline__ void unpack2(u64 v, float& lo, float& hi) {
    asm("mov.b64 {%0, %1}, %2;" : "=f"(lo), "=f"(hi) : "l"(v));
}
__device__ __forceinline__ u64 lds64(uint32_t a) {
    u64 v; asm volatile("ld.shared.u64 %0, [%1];" : "=l"(v) : "r"(a)); return v;
}
__device__ __forceinline__ void lds_v2(uint32_t a, u64& x, u64& y) {
    asm volatile("ld.shared.v2.u64 {%0, %1}, [%2];" : "=l"(x), "=l"(y) : "r"(a));
}
__device__ __forceinline__ void sts64(uint32_t a, u64 v) {
    asm volatile("st.shared.u64 [%0], %1;" :: "r"(a), "l"(v) : "memory");
}

// 64x152 = XT(150 k) @ W(150x152); warp = 8-col group, lane = row pair.
// Depth-3 rotating register pipeline: slot s holds k+s; consume slot, refill
// with k+3 -> load-to-use distance ~2 slots (~28 instr) covering LDS latency.
__device__ __forceinline__ void gemm_pair(uint32_t xt_b, uint32_t w_b, uint32_t bias_b,
                                          int rg, int c0, u64 acc[2][4])
{
#pragma unroll
    for (int cp = 0; cp < 4; cp++) {
        u64 bv = lds64(bias_b + (uint32_t)(c0 + 2 * cp) * 4u);
        acc[0][cp] = bv; acc[1][cp] = bv;
    }
    const uint32_t xa = xt_b + (uint32_t)(2 * rg) * 4u;   // + k*256B
    const uint32_t wa = w_b + (uint32_t)c0 * 4u;          // + k*608B

    u64 px[3]; u64 pw[3][4];
#pragma unroll
    for (int s = 0; s < 3; s++) {
        px[s] = lds64(xa + (uint32_t)s * 256u);
        lds_v2(wa + (uint32_t)s * 608u,       pw[s][0], pw[s][1]);
        lds_v2(wa + (uint32_t)s * 608u + 16u, pw[s][2], pw[s][3]);
    }
#pragma unroll 1
    for (int k = 0; k < C_; k += 3) {
#pragma unroll
        for (int s = 0; s < 3; s++) {
            float x0, x1; unpack2(px[s], x0, x1);
            u64 d0 = dup2(x0), d1 = dup2(x1);
            ffma2(acc[0][0], d0, pw[s][0]); ffma2(acc[0][1], d0, pw[s][1]);
            ffma2(acc[0][2], d0, pw[s][2]); ffma2(acc[0][3], d0, pw[s][3]);
            ffma2(acc[1][0], d1, pw[s][0]); ffma2(acc[1][1], d1, pw[s][1]);
            ffma2(acc[1][2], d1, pw[s][2]); ffma2(acc[1][3], d1, pw[s][3]);
            int kn = k + s + 3;
            if (kn < C_) {
                px[s] = lds64(xa + (uint32_t)kn * 256u);
                lds_v2(wa + (uint32_t)kn * 608u,       pw[s][0], pw[s][1]);
                lds_v2(wa + (uint32_t)kn * 608u + 16u, pw[s][2], pw[s][3]);
            }
        }
    }
}

__global__ __launch_bounds__(NTHR, 1)
void grapher_kernel(const int* __restrict__ ids,
                    const float* __restrict__ feat,
                    const float* __restrict__ W1, const float* __restrict__ b1,
                    const float* __restrict__ Wm, const float* __restrict__ bm,
                    const float* __restrict__ W2, const float* __restrict__ b2,
                    float* __restrict__ out)
{
    extern __shared__ float sm[];
    float* sWm = sm + OFF_WM;
    float* sW2 = sm + OFF_W2;
    float* sX  = sm + OFF_X;
    float* sG  = sm + OFF_G;
    float* sB1 = sm + OFF_B1;
    float* sBM = sm + OFF_BM;
    float* sB2 = sm + OFF_B2;
    int*   sBnd = (int*)(sm + OFF_BND);

    const int tid = threadIdx.x;
    const int b   = blockIdx.x;
    const uint32_t wm_b = sptr(sWm);
    const uint32_t w2_b = sptr(sW2);
    const uint32_t x_b  = sptr(sX);

    // ---------- cp.async prefetch Wm + W2 (dest stride 152, src 150) ----------
    for (int m = tid; m < C_ * 75; m += NTHR) {
        int r = m / 75, cl = m - r * 75;
        cp8(wm_b + (uint32_t)(r * 152 + 2 * cl) * 4u, Wm + r * C_ + 2 * cl);
        cp8(w2_b + (uint32_t)(r * 152 + 2 * cl) * 4u, W2 + r * C_ + 2 * cl);
    }
    CP_COMMIT();
    if (tid < C_) {
        sWm[tid * 152 + 150] = 0.f; sWm[tid * 152 + 151] = 0.f;
        sW2[tid * 152 + 150] = 0.f; sW2[tid * 152 + 151] = 0.f;
    }

    // ---------- separator scan (warp 0) + bias loads ----------
    if (tid < 32) {
        const int lane = tid;
        if (lane < 16) sBnd[lane] = S_;
        __syncwarp();
        const int4* rp = (const int4*)(ids + (size_t)b * S_) + lane * 8;
        int4 v[8];
        int cnt = 0;
#pragma unroll
        for (int q = 0; q < 8; q++) {
            v[q] = rp[q];
            cnt += (v[q].x == SEPID) + (v[q].y == SEPID) +
                   (v[q].z == SEPID) + (v[q].w == SEPID);
        }
        int pre = cnt;
#pragma unroll
        for (int off = 1; off < 32; off <<= 1) {
            int t = __shfl_up_sync(0xffffffffu, pre, off);
            if (lane >= off) pre += t;
        }
        int run = pre - cnt;
#pragma unroll
        for (int q = 0; q < 8; q++) {
            int base = lane * 32 + q * 4;
            if (v[q].x == SEPID) { run++; if (run <= NN) sBnd[run] = base + 0; }
            if (v[q].y == SEPID) { run++; if (run <= NN) sBnd[run] = base + 1; }
            if (v[q].z == SEPID) { run++; if (run <= NN) sBnd[run] = base + 2; }
            if (v[q].w == SEPID) { run++; if (run <= NN) sBnd[run] = base + 3; }
        }
    } else if (tid >= 448 && tid < 448 + 152) {
        int i = tid - 448;
        sB1[i] = (i < C_) ? b1[i] : 0.f;
        sBM[i] = (i < C_) ? bm[i] : 0.f;
        sB2[i] = (i < C_) ? b2[i] : 0.f;
    }
    __syncthreads();

    // ---------- segment means -> meansT[k][8] in sX (R3 form) ----------
    if (tid < 384) {
        const float2* f2 = (const float2*)(feat + (size_t)b * S_ * H_) + tid;
#pragma unroll 1
        for (int n = 0; n < NN; n++) {
            int lo = (n == 0) ? 0 : sBnd[n] + 1;
            int hi = sBnd[n + 1];
            float2 a0 = make_float2(0.f, 0.f), a1 = a0, a2 = a0, a3 = a0;
            int t = lo;
            for (; t + 3 < hi; t += 4) {
                float2 v0 = f2[(t + 0) * 384];
                float2 v1 = f2[(t + 1) * 384];
                float2 v2 = f2[(t + 2) * 384];
                float2 v3 = f2[(t + 3) * 384];
                a0.x += v0.x; a0.y += v0.y;
                a1.x += v1.x; a1.y += v1.y;
                a2.x += v2.x; a2.y += v2.y;
                a3.x += v3.x; a3.y += v3.y;
            }
            for (; t < hi; t++) {
                float2 v = f2[t * 384];
                a0.x += v.x; a0.y += v.y;
            }
            float sx = (a0.x + a1.x) + (a2.x + a3.x);
            float sy = (a0.y + a1.y) + (a2.y + a3.y);
            int c = hi - lo; if (c < 1) c = 1;
            float inv = 1.0f / (float)c;
            sX[(2 * tid + 0) * 8 + n] = sx * inv;
            sX[(2 * tid + 1) * 8 + n] = sy * inv;
        }
    }
    __syncthreads();

    // ---------- GEMM1: g[n][c] = sum_k meansT[k][n] * W1[k][c] ----------
    // Double-buffered groups of 8 W1 LDGs (float2 each) to cover L2 latency.
    u64 g_acc[2][4];
    int ks = 0, cpair = 0;
    if (tid < 600) {
        ks = tid / 75; cpair = tid - ks * 75;
#pragma unroll
        for (int cc = 0; cc < 2; cc++)
#pragma unroll
            for (int q = 0; q < 4; q++) g_acc[cc][q] = 0ull;
        const float2* wrow = (const float2*)(W1 + (size_t)(ks * 96) * C_) + cpair;
        float2 wb0[8], wb1[8];
#pragma unroll
        for (int i = 0; i < 8; i++) wb0[i] = __ldg(wrow + i * 75);

#pragma unroll 1
        for (int g = 0; g < 12; g += 2) {
            // prefetch group g+1 into wb1
#pragma unroll
            for (int i = 0; i < 8; i++) wb1[i] = __ldg(wrow + ((g + 1) * 8 + i) * 75);
            // compute group g from wb0
#pragma unroll
            for (int i = 0; i < 8; i++) {
                int k = ks * 96 + g * 8 + i;
                u64 dw0 = dup2(wb0[i].x), dw1 = dup2(wb0[i].y);
                u64 m01, m23, m45, m67;
                uint32_t ma = x_b + (uint32_t)(k * 8) * 4u;
                lds_v2(ma, m01, m23);
                lds_v2(ma + 16u, m45, m67);
                ffma2(g_acc[0][0], m01, dw0); ffma2(g_acc[0][1], m23, dw0);
                ffma2(g_acc[0][2], m45, dw0); ffma2(g_acc[0][3], m67, dw0);
                ffma2(g_acc[1][0], m01, dw1); ffma2(g_acc[1][1], m23, dw1);
                ffma2(g_acc[1][2], m45, dw1); ffma2(g_acc[1][3], m67, dw1);
            }
            // prefetch group g+2 into wb0
            if (g + 2 < 12) {
#pragma unroll
                for (int i = 0; i < 8; i++) wb0[i] = __ldg(wrow + ((g + 2) * 8 + i) * 75);
            }
            // compute group g+1 from wb1
#pragma unroll
            for (int i = 0; i < 8; i++) {
                int k = ks * 96 + (g + 1) * 8 + i;
                u64 dw0 = dup2(wb1[i].x), dw1 = dup2(wb1[i].y);
                u64 m01, m23, m45, m67;
                uint32_t ma = x_b + (uint32_t)(k * 8) * 4u;
                lds_v2(ma, m01, m23);
                lds_v2(ma + 16u, m45, m67);
                ffma2(g_acc[0][0], m01, dw0); ffma2(g_acc[0][1], m23, dw0);
                ffma2(g_acc[0][2], m45, dw0); ffma2(g_acc[0][3], m67, dw0);
                ffma2(g_acc[1][0], m01, dw1); ffma2(g_acc[1][1], m23, dw1);
                ffma2(g_acc[1][2], m45, dw1); ffma2(g_acc[1][3], m67, dw1);
            }
        }
    }
    __syncthreads();                      // meansT reads done; reuse region
    if (tid < 600) {                      // partials P[ks][e][150]
#pragma unroll
        for (int cc = 0; cc < 2; cc++)
#pragma unroll
            for (int q = 0; q < 4; q++)
                sts64(x_b + (uint32_t)(ks * 1200 + (cc * 4 + q) * 150 + 2 * cpair) * 4u,
                      g_acc[cc][q]);
    }
    __syncthreads();
    if (tid < 600) {                      // reduce 8 slices -> sG
        u64 s = lds64(x_b + (uint32_t)(2 * tid) * 4u);
#pragma unroll
        for (int k8 = 1; k8 < 8; k8++)
            s = add2(s, lds64(x_b + (uint32_t)(k8 * 1200 + 2 * tid) * 4u));
        int e = tid / 75, cp2 = tid - e * 75;
        int cc = e >> 2, q = e & 3, c = 2 * cp2 + cc;
        float lo, hi; unpack2(s, lo, hi);
        sG[(2 * q + 0) * 152 + c] = lo;
        sG[(2 * q + 1) * 152 + c] = hi;
    }
    CP_WAIT0();                           // Wm/W2 resident before GEMM2
    __syncthreads();

    // ---------- pair build: XT[c][p] = relu(g_i[c] - g_j[c] + b1[c]) ----------
    const int cg = tid >> 5;              // warp -> col group of 8
    const int rg = tid & 31;              // row pair 2rg, 2rg+1
    const int c0 = cg * 8;
    {
        float v[2][8];
#pragma unroll
        for (int r = 0; r < 2; r++) {
            int p = 2 * rg + r;
            int i = p >> 3, j = p & 7;
            float4 ga0 = *(const float4*)(sG + i * 152 + c0);
            float4 ga1 = *(const float4*)(sG + i * 152 + c0 + 4);
            float4 gb0 = *(const float4*)(sG + j * 152 + c0);
            float4 gb1 = *(const float4*)(sG + j * 152 + c0 + 4);
            float4 ba  = *(const float4*)(sB1 + c0);
            float4 bb  = *(const float4*)(sB1 + c0 + 4);
            v[r][0] = fmaxf(ga0.x - gb0.x + ba.x, 0.f);
            v[r][1] = fmaxf(ga0.y - gb0.y + ba.y, 0.f);
            v[r][2] = fmaxf(ga0.z - gb0.z + ba.z, 0.f);
            v[r][3] = fmaxf(ga0.w - gb0.w + ba.w, 0.f);
            v[r][4] = fmaxf(ga1.x - gb1.x + bb.x, 0.f);
            v[r][5] = fmaxf(ga1.y - gb1.y + bb.y, 0.f);
            v[r][6] = fmaxf(ga1.z - gb1.z + bb.z, 0.f);
            v[r][7] = fmaxf(ga1.w - gb1.w + bb.w, 0.f);
        }
#pragma unroll
        for (int ccj = 0; ccj < 8; ccj++)
            sts64(x_b + (uint32_t)((c0 + ccj) * 64 + 2 * rg) * 4u,
                  pack2(v[0][ccj], v[1][ccj]));
    }
    __syncthreads();

    // ---------- GEMM2: y = relu(x @ Wm + bm) ----------
    u64 acc[2][4];
    gemm_pair(x_b, wm_b, sptr(sBM), rg, c0, acc);
    __syncthreads();                      // all x reads done
#pragma unroll
    for (int r = 0; r < 2; r++) {
        int p = 2 * rg + r;
#pragma unroll
        for (int cp = 0; cp < 4; cp++) {
            float lo, hi; unpack2(acc[r][cp], lo, hi);
            sX[(c0 + 2 * cp + 0) * 64 + p] = fmaxf(lo, 0.f);
            sX[(c0 + 2 * cp + 1) * 64 + p] = fmaxf(hi, 0.f);
        }
    }
    __syncthreads();

    // ---------- GEMM3: out = y @ W2 + b2 ----------
    gemm_pair(x_b, w2_b, sptr(sB2), rg, c0, acc);

    const int ncp = (cg < 18) ? 4 : 3;    // col group 18 covers 144..149
#pragma unroll
    for (int r = 0; r < 2; r++) {
        int p = 2 * rg + r;
        float* o = out + ((size_t)p * B_ + b) * C_ + c0;
        for (int cp = 0; cp < ncp; cp++) {
            float lo, hi; unpack2(acc[r][cp], lo, hi);
            *(float2*)(o + 2 * cp) = make_float2(lo, hi);
        }
    }
}

extern "C" void kernel_launch(void* const* d_in, const int* in_sizes, int n_in,
                              void* d_out, int out_size)
{
    const int*   ids  = (const int*)d_in[0];
    const float* feat = (const float*)d_in[1];
    const float* W1 = (const float*)d_in[2];
    const float* b1 = (const float*)d_in[3];
    const float* Wm = (const float*)d_in[4];
    const float* bm = (const float*)d_in[5];
    const float* W2 = (const float*)d_in[6];
    const float* b2 = (const float*)d_in[7];
    float* out = (float*)d_out;

    cudaFuncSetAttribute(grapher_kernel,
                         cudaFuncAttributeMaxDynamicSharedMemorySize, SMEM_BYTES);
    grapher_kernel<<<B_, NTHR, SMEM_BYTES>>>(ids, feat, W1, b1, Wm, bm, W2, b2, out);
}

// round 7
// speedup vs baseline: 1.0400x; 1.0031x over previous
#include <cuda_runtime.h>
#include <cstdint>

// Grapher: B=128, S=1024, H=768, C=150, N=8, sep id 3. One block per batch.
// fp32 with packed f32x2 FFMA. Round-7: contiguous-tile token-parallel means
// (3 tiles x 192 float4 cols, 4-unrolled => MLP 12 effective), partials in the
// W2 smem region, deferred W2 cp.async, W1 L2-prefetch by the spare warp.

#define B_   128
#define S_   1024
#define H_   768
#define C_   150
#define NN   8
#define SEPID 3
#define NTHR 608          // 19 warps

// shared memory layout (float offsets)
#define OFF_WM    0        // 150*152 = 22800 (cols 150,151 zero pad)
#define OFF_W2    22800    // 150*152 ; during means: partials P[3][8][776] = 18624
#define OFF_X     45600    // 9728: meansT[768][8] -> GEMM1 partials -> XT[152][64]
#define OFF_G     55328    // 8*152
#define OFF_B1    56544    // 152
#define OFF_BM    56696    // 152
#define OFF_B2    56848    // 152
#define OFF_BND   57000    // 16 ints
#define SMEM_FLOATS 57016
#define SMEM_BYTES (SMEM_FLOATS * 4)   // 228064 <= 232448

typedef unsigned long long u64;

__device__ __forceinline__ uint32_t sptr(const void* p) {
    return (uint32_t)__cvta_generic_to_shared(p);
}
__device__ __forceinline__ void cp8(uint32_t s, const void* g) {
    asm volatile("cp.async.ca.shared.global [%0], [%1], 8;" :: "r"(s), "l"(g));
}
#define CP_COMMIT() asm volatile("cp.async.commit_group;" ::: "memory")
#define CP_WAIT1()  asm volatile("cp.async.wait_group 1;" ::: "memory")
#define CP_WAIT0()  asm volatile("cp.async.wait_group 0;" ::: "memory")

__device__ __forceinline__ void ffma2(u64& d, u64 a, u64 b) {
    asm("fma.rn.f32x2 %0, %1, %2, %0;" : "+l"(d) : "l"(a), "l"(b));
}
__device__ __forceinline__ u64 add2(u64 a, u64 b) {
    u64 r; asm("add.rn.f32x2 %0, %1, %2;" : "=l"(r) : "l"(a), "l"(b)); return r;
}
__device__ __forceinline__ u64 dup2(float x) {
    u64 r; asm("mov.b64 %0, {%1, %1};" : "=l"(r) : "f"(x)); return r;
}
__device__ __forceinline__ u64 pack2(float lo, float hi) {
    u64 r; asm("mov.b64 %0, {%1, %2};" : "=l"(r) : "f"(lo), "f"(hi)); return r;
}
__device__ __forceinline__ void unpack2(u64 v, float& lo, float& hi) {
    asm("mov.b64 {%0, %1}, %2;" : "=f"(lo), "=f"(hi) : "l"(v));
}
__device__ __forceinline__ u64 lds64(uint32_t a) {
    u64 v; asm volatile("ld.shared.u64 %0, [%1];" : "=l"(v) : "r"(a)); return v;
}
__device__ __forceinline__ void lds_v2(uint32_t a, u64& x, u64& y) {
    asm volatile("ld.shared.v2.u64 {%0, %1}, [%2];" : "=l"(x), "=l"(y) : "r"(a));
}
__device__ __forceinline__ void sts64(uint32_t a, u64 v) {
    asm volatile("st.shared.u64 [%0], %1;" :: "r"(a), "l"(v) : "memory");
}

// 64x152 = XT(150 k) @ W(150x152); warp = 8-col group, lane = row pair.
__device__ __forceinline__ void gemm_pair(uint32_t xt_b, uint32_t w_b, uint32_t bias_b,
                                          int rg, int c0, u64 acc[2][4])
{
#pragma unroll
    for (int cp = 0; cp < 4; cp++) {
        u64 bv = lds64(bias_b + (uint32_t)(c0 + 2 * cp) * 4u);
        acc[0][cp] = bv; acc[1][cp] = bv;
    }
#pragma unroll 6
    for (int k = 0; k < C_; k++) {
        u64 xp = lds64(xt_b + (uint32_t)(k * 64 + 2 * rg) * 4u);
        float x0, x1; unpack2(xp, x0, x1);
        u64 d0 = dup2(x0), d1 = dup2(x1);
        u64 w0, w1, w2, w3;
        uint32_t wa = w_b + (uint32_t)(k * 152 + c0) * 4u;
        lds_v2(wa, w0, w1);
        lds_v2(wa + 16u, w2, w3);
        ffma2(acc[0][0], d0, w0); ffma2(acc[0][1], d0, w1);
        ffma2(acc[0][2], d0, w2); ffma2(acc[0][3], d0, w3);
        ffma2(acc[1][0], d1, w0); ffma2(acc[1][1], d1, w1);
        ffma2(acc[1][2], d1, w2); ffma2(acc[1][3], d1, w3);
    }
}

__global__ __launch_bounds__(NTHR, 1)
void grapher_kernel(const int* __restrict__ ids,
                    const float* __restrict__ feat,
                    const float* __restrict__ W1, const float* __restrict__ b1,
                    const float* __restrict__ Wm, const float* __restrict__ bm,
                    const float* __restrict__ W2, const float* __restrict__ b2,
                    float* __restrict__ out)
{
    extern __shared__ float sm[];
    float* sWm = sm + OFF_WM;
    float* sW2 = sm + OFF_W2;            // P scratch during means
    float* sX  = sm + OFF_X;
    float* sG  = sm + OFF_G;
    float* sB1 = sm + OFF_B1;
    float* sBM = sm + OFF_BM;
    float* sB2 = sm + OFF_B2;
    int*   sBnd = (int*)(sm + OFF_BND);

    const int tid = threadIdx.x;
    const int b   = blockIdx.x;
    const uint32_t wm_b = sptr(sWm);
    const uint32_t w2_b = sptr(sW2);
    const uint32_t x_b  = sptr(sX);

    // ---------- cp.async group A: Wm ----------
    for (int m = tid; m < C_ * 75; m += NTHR) {
        int r = m / 75, cl = m - r * 75;
        cp8(wm_b + (uint32_t)(r * 152 + 2 * cl) * 4u, Wm + r * C_ + 2 * cl);
    }
    CP_COMMIT();
    if (tid < C_) { sWm[tid * 152 + 150] = 0.f; sWm[tid * 152 + 151] = 0.f; }

    // ---------- separator scan (warp 0) + bias loads ----------
    if (tid < 32) {
        const int lane = tid;
        if (lane < 16) sBnd[lane] = S_;
        __syncwarp();
        const int4* rp = (const int4*)(ids + (size_t)b * S_) + lane * 8;
        int4 v[8];
        int cnt = 0;
#pragma unroll
        for (int q = 0; q < 8; q++) {
            v[q] = rp[q];
            cnt += (v[q].x == SEPID) + (v[q].y == SEPID) +
                   (v[q].z == SEPID) + (v[q].w == SEPID);
        }
        int pre = cnt;
#pragma unroll
        for (int off = 1; off < 32; off <<= 1) {
            int t = __shfl_up_sync(0xffffffffu, pre, off);
            if (lane >= off) pre += t;
        }
        int run = pre - cnt;
#pragma unroll
        for (int q = 0; q < 8; q++) {
            int base = lane * 32 + q * 4;
            if (v[q].x == SEPID) { run++; if (run <= NN) sBnd[run] = base + 0; }
            if (v[q].y == SEPID) { run++; if (run <= NN) sBnd[run] = base + 1; }
            if (v[q].z == SEPID) { run++; if (run <= NN) sBnd[run] = base + 2; }
            if (v[q].w == SEPID) { run++; if (run <= NN) sBnd[run] = base + 3; }
        }
    } else if (tid >= 448 && tid < 448 + 152) {
        int i = tid - 448;
        sB1[i] = (i < C_) ? b1[i] : 0.f;
        sBM[i] = (i < C_) ? bm[i] : 0.f;
        sB2[i] = (i < C_) ? b2[i] : 0.f;
    }
    __syncthreads();

    // ---------- means partials: 3 contiguous token tiles x 192 float4 cols ----
    if (tid < 576) {
        const int tg  = tid / 192;
        const int col = tid - tg * 192;
        const int T   = sBnd[NN];            // all relevant tokens are < T
        const int tb0 = (T * tg) / 3;
        const int tb1 = (T * (tg + 1)) / 3;
        const float4* f4 = (const float4*)(feat + (size_t)b * S_ * H_) + col;
        float* P = sW2 + tg * 6208 + col * 4;
#pragma unroll 1
        for (int n = 0; n < NN; n++) {
            int lo = (n == 0) ? 0 : sBnd[n] + 1;
            int hi = sBnd[n + 1];
            if (lo < tb0) lo = tb0;
            if (hi > tb1) hi = tb1;
            float4 a0 = make_float4(0.f, 0.f, 0.f, 0.f), a1 = a0, a2 = a0, a3 = a0;
            int t = lo;
            for (; t + 3 < hi; t += 4) {
                float4 v0 = f4[(t + 0) * 192];
                float4 v1 = f4[(t + 1) * 192];
                float4 v2 = f4[(t + 2) * 192];
                float4 v3 = f4[(t + 3) * 192];
                a0.x += v0.x; a0.y += v0.y; a0.z += v0.z; a0.w += v0.w;
                a1.x += v1.x; a1.y += v1.y; a1.z += v1.z; a1.w += v1.w;
                a2.x += v2.x; a2.y += v2.y; a2.z += v2.z; a2.w += v2.w;
                a3.x += v3.x; a3.y += v3.y; a3.z += v3.z; a3.w += v3.w;
            }
            for (; t < hi; t++) {
                float4 v = f4[t * 192];
                a0.x += v.x; a0.y += v.y; a0.z += v.z; a0.w += v.w;
            }
            float4 s;
            s.x = (a0.x + a1.x) + (a2.x + a3.x);
            s.y = (a0.y + a1.y) + (a2.y + a3.y);
            s.z = (a0.z + a1.z) + (a2.z + a3.z);
            s.w = (a0.w + a1.w) + (a2.w + a3.w);
            *(float4*)(P + n * 776) = s;
        }
    } else {
        // spare warp: prefetch W1 into L2 for GEMM1 (shared across all blocks)
        const float4* w4 = (const float4*)W1;
        for (int i = tid - 576; i < (H_ * C_) / 4; i += 32)
            asm volatile("prefetch.global.L2 [%0];" :: "l"(w4 + i));
    }
    __syncthreads();

    // ---------- combine tiles + 1/len -> meansT[k][8] in sX ----------
    {
        float inv[8];
#pragma unroll
        for (int n = 0; n < NN; n++) {
            int lo = (n == 0) ? 0 : sBnd[n] + 1;
            int len = sBnd[n + 1] - lo;
            if (len < 1) len = 1;
            inv[n] = 1.0f / (float)len;
        }
        for (int k = tid; k < H_; k += NTHR) {
            const float* P = sW2 + k;
#pragma unroll
            for (int n = 0; n < NN; n++) {
                float s = P[n * 776] + P[6208 + n * 776] + P[12416 + n * 776];
                sX[k * 8 + n] = s * inv[n];
            }
        }
    }
    __syncthreads();                      // P reads done; W2 region free

    // ---------- cp.async group B: W2 (overlaps GEMM1/pair/GEMM2) ----------
    for (int m = tid; m < C_ * 75; m += NTHR) {
        int r = m / 75, cl = m - r * 75;
        cp8(w2_b + (uint32_t)(r * 152 + 2 * cl) * 4u, W2 + r * C_ + 2 * cl);
    }
    CP_COMMIT();
    if (tid < C_) { sW2[tid * 152 + 150] = 0.f; sW2[tid * 152 + 151] = 0.f; }

    // ---------- GEMM1: g[n][c] = sum_k meansT[k][n] * W1[k][c] ----------
    u64 g_acc[2][4];
    int ks = 0, cpair = 0;
    if (tid < 600) {
        ks = tid / 75; cpair = tid - ks * 75;
#pragma unroll
        for (int cc = 0; cc < 2; cc++)
#pragma unroll
            for (int q = 0; q < 4; q++) g_acc[cc][q] = 0ull;
        const float2* wrow = (const float2*)(W1 + (size_t)(ks * 96) * C_) + cpair;
#pragma unroll 4
        for (int kk = 0; kk < 96; kk++) {
            int k = ks * 96 + kk;
            float2 w = __ldg(wrow + kk * 75);
            u64 dw0 = dup2(w.x), dw1 = dup2(w.y);
            u64 m01, m23, m45, m67;
            uint32_t ma = x_b + (uint32_t)(k * 8) * 4u;
            lds_v2(ma, m01, m23);
            lds_v2(ma + 16u, m45, m67);
            ffma2(g_acc[0][0], m01, dw0); ffma2(g_acc[0][1], m23, dw0);
            ffma2(g_acc[0][2], m45, dw0); ffma2(g_acc[0][3], m67, dw0);
            ffma2(g_acc[1][0], m01, dw1); ffma2(g_acc[1][1], m23, dw1);
            ffma2(g_acc[1][2], m45, dw1); ffma2(g_acc[1][3], m67, dw1);
        }
    }
    __syncthreads();                      // meansT reads done; reuse region
    if (tid < 600) {                      // partials P[ks][e][150]
#pragma unroll
        for (int cc = 0; cc < 2; cc++)
#pragma unroll
            for (int q = 0; q < 4; q++)
                sts64(x_b + (uint32_t)(ks * 1200 + (cc * 4 + q) * 150 + 2 * cpair) * 4u,
                      g_acc[cc][q]);
    }
    __syncthreads();
    if (tid < 600) {                      // reduce 8 slices -> sG
        u64 s = lds64(x_b + (uint32_t)(2 * tid) * 4u);
#pragma unroll
        for (int k8 = 1; k8 < 8; k8++)
            s = add2(s, lds64(x_b + (uint32_t)(k8 * 1200 + 2 * tid) * 4u));
        int e = tid / 75, cp2 = tid - e * 75;
        int cc = e >> 2, q = e & 3, c = 2 * cp2 + cc;
        float lo, hi; unpack2(s, lo, hi);
        sG[(2 * q + 0) * 152 + c] = lo;
        sG[(2 * q + 1) * 152 + c] = hi;
    }
    CP_WAIT1();                           // Wm (group A) resident
    __syncthreads();

    // ---------- pair build: XT[c][p] = relu(g_i[c] - g_j[c] + b1[c]) ----------
    const int cg = tid >> 5;              // warp -> col group of 8
    const int rg = tid & 31;              // row pair 2rg, 2rg+1
    const int c0 = cg * 8;
    {
        float v[2][8];
#pragma unroll
        for (int r = 0; r < 2; r++) {
            int p = 2 * rg + r;
            int i = p >> 3, j = p & 7;
            float4 ga0 = *(const float4*)(sG + i * 152 + c0);
            float4 ga1 = *(const float4*)(sG + i * 152 + c0 + 4);
            float4 gb0 = *(const float4*)(sG + j * 152 + c0);
            float4 gb1 = *(const float4*)(sG + j * 152 + c0 + 4);
            float4 ba  = *(const float4*)(sB1 + c0);
            float4 bb  = *(const float4*)(sB1 + c0 + 4);
            v[r][0] = fmaxf(ga0.x - gb0.x + ba.x, 0.f);
            v[r][1] = fmaxf(ga0.y - gb0.y + ba.y, 0.f);
            v[r][2] = fmaxf(ga0.z - gb0.z + ba.z, 0.f);
            v[r][3] = fmaxf(ga0.w - gb0.w + ba.w, 0.f);
            v[r][4] = fmaxf(ga1.x - gb1.x + bb.x, 0.f);
            v[r][5] = fmaxf(ga1.y - gb1.y + bb.y, 0.f);
            v[r][6] = fmaxf(ga1.z - gb1.z + bb.z, 0.f);
            v[r][7] = fmaxf(ga1.w - gb1.w + bb.w, 0.f);
        }
#pragma unroll
        for (int ccj = 0; ccj < 8; ccj++)
            sts64(x_b + (uint32_t)((c0 + ccj) * 64 + 2 * rg) * 4u,
                  pack2(v[0][ccj], v[1][ccj]));
    }
    __syncthreads();

    // ---------- GEMM2: y = relu(x @ Wm + bm) ----------
    u64 acc[2][4];
    gemm_pair(x_b, wm_b, sptr(sBM), rg, c0, acc);
    __syncthreads();                      // all x reads done
#pragma unroll
    for (int r = 0; r < 2; r++) {
        int p = 2 * rg + r;
#pragma unroll
        for (int cp = 0; cp < 4; cp++) {
            float lo, hi; unpack2(acc[r][cp], lo, hi);
            sX[(c0 + 2 * cp + 0) * 64 + p] = fmaxf(lo, 0.f);
            sX[(c0 + 2 * cp + 1) * 64 + p] = fmaxf(hi, 0.f);
        }
    }
    CP_WAIT0();                           // W2 (group B) resident
    __syncthreads();

    // ---------- GEMM3: out = y @ W2 + b2 ----------
    gemm_pair(x_b, w2_b, sptr(sB2), rg, c0, acc);

    const int ncp = (cg < 18) ? 4 : 3;    // col group 18 covers 144..149
#pragma unroll
    for (int r = 0; r < 2; r++) {
        int p = 2 * rg + r;
        float* o = out + ((size_t)p * B_ + b) * C_ + c0;
        for (int cp = 0; cp < ncp; cp++) {
            float lo, hi; unpack2(acc[r][cp], lo, hi);
            *(float2*)(o + 2 * cp) = make_float2(lo, hi);
        }
    }
}

extern "C" void kernel_launch(void* const* d_in, const int* in_sizes, int n_in,
                              void* d_out, int out_size)
{
    const int*   ids  = (const int*)d_in[0];
    const float* feat = (const float*)d_in[1];
    const float* W1 = (const float*)d_in[2];
    const float* b1 = (const float*)d_in[3];
    const float* Wm = (const float*)d_in[4];
    const float* bm = (const float*)d_in[5];
    const float* W2 = (const float*)d_in[6];
    const float* b2 = (const float*)d_in[7];
    float* out = (float*)d_out;

    cudaFuncSetAttribute(grapher_kernel,
                         cudaFuncAttributeMaxDynamicSharedMemorySize, SMEM_BYTES);
    grapher_kernel<<<B_, NTHR, SMEM_BYTES>>>(ids, feat, W1, b1, Wm, bm, W2, b2, out);
}